// round 13
// baseline (speedup 1.0000x reference)
#include <cuda_runtime.h>
#include <cuda_fp16.h>
#include <cstdint>

// ---------------- problem constants ----------------
#define N_    32
#define C_    128
#define H_    56
#define W_    56
#define K_    256
#define HW_   3136
#define HP_   58
#define WP_   58
#define TPI   784            // winograd tiles per image (28*28)
#define P_TOT 25088          // 32 * 784

// ---------------- fused GEMM tiling ----------------
#define GBM   128            // k-out per CTA
#define GBN   64             // winograd tiles per CTA
#define NST   16             // 16 xi, one full-K stage each (BK=128)
#define PITCH 136            // halves per smem row (128 + 8) -> conflict-free
#define SA_BYTES (GBM * PITCH * 2)              // 34816
#define SB_BYTES (GBN * PITCH * 2)              // 17408
#define STAGE_BYTES (SA_BYTES + SB_BYTES)       // 52224
#define SMEM_TOTAL (3 * STAGE_BYTES)            // 156672

// ---------------- scratch ----------------
__device__ alignas(1024) __half g_xp[(size_t)N_ * HP_ * WP_ * C_];       // padded NHWC fp16
__device__ alignas(1024) __half g_U[16 * K_ * C_];                       // wino weights [xi][k][c]
__device__ alignas(1024) __half g_V[(size_t)16 * P_TOT * C_];            // wino inputs  [xi][p][c]

// ---------------- helpers ----------------
__device__ __forceinline__ uint32_t smem_u32(const void* p) {
    uint32_t a;
    asm("{ .reg .u64 t; cvta.to.shared.u64 t, %1; cvt.u32.u64 %0, t; }" : "=r"(a) : "l"(p));
    return a;
}
#define CP16(dst, src) \
    asm volatile("cp.async.cg.shared.global [%0], [%1], 16;" :: "r"(dst), "l"(src) : "memory")
#define CP_COMMIT() asm volatile("cp.async.commit_group;" ::: "memory")
#define CP_WAIT1()  asm volatile("cp.async.wait_group 1;" ::: "memory")
#define CP_WAIT0()  asm volatile("cp.async.wait_group 0;" ::: "memory")
#define LDSM_X4(r0, r1, r2, r3, addr) \
    asm volatile("ldmatrix.sync.aligned.m8n8.x4.shared.b16 {%0,%1,%2,%3}, [%4];" \
        : "=r"(r0), "=r"(r1), "=r"(r2), "=r"(r3) : "r"(addr))

__device__ __forceinline__ float quant16f(float x) {
    float r = rintf(x * 4096.0f);
    r = fminf(fmaxf(r, -32768.0f), 32767.0f);
    return r * (1.0f / 4096.0f);
}

// ---------------- prepass: quantize + pad input ----------------
__global__ void zero_border_kernel() {
    int b = blockIdx.x;              // 32*58
    int n = b / HP_, hp = b % HP_;
    __half* rowp = g_xp + ((size_t)(n * HP_ + hp)) * WP_ * C_;
    uint4 z = make_uint4(0, 0, 0, 0);
    if (hp == 0 || hp == HP_ - 1) {
        for (int i = threadIdx.x; i < WP_ * C_ / 8; i += blockDim.x)
            reinterpret_cast<uint4*>(rowp)[i] = z;
    } else {
        if (threadIdx.x < 32) {
            int side = threadIdx.x >> 4;
            int q    = threadIdx.x & 15;
            __half* colp = rowp + (side ? (size_t)(WP_ - 1) * C_ : 0);
            reinterpret_cast<uint4*>(colp)[q] = z;
        }
    }
}

__global__ void xform_x_kernel(const float* __restrict__ x) {
    __shared__ __half st[W_ * C_];
    const int n = blockIdx.x, h = blockIdx.y;
    const int tid = threadIdx.x;
    const int c  = tid >> 1;
    const int wh = (tid & 1) * 28;
    const float* src = x + ((size_t)(n * C_ + c) * H_ + h) * W_ + wh;
    #pragma unroll
    for (int j = 0; j < 7; ++j) {
        float4 v = *reinterpret_cast<const float4*>(src + 4 * j);
        int wb = wh + 4 * j;
        st[(wb + 0) * C_ + c] = __float2half_rn(quant16f(v.x));
        st[(wb + 1) * C_ + c] = __float2half_rn(quant16f(v.y));
        st[(wb + 2) * C_ + c] = __float2half_rn(quant16f(v.z));
        st[(wb + 3) * C_ + c] = __float2half_rn(quant16f(v.w));
    }
    __syncthreads();
    __half* dst = g_xp + ((size_t)((n * HP_ + h + 1) * WP_ + 1)) * C_;
    for (int idx = tid; idx < W_ * C_ / 8; idx += 256) {
        int w = idx >> 4, q = idx & 15;
        reinterpret_cast<uint4*>(dst + (size_t)w * C_)[q] =
            reinterpret_cast<const uint4*>(st + w * C_)[q];
    }
}

// ---------------- weight transform: U = G g G^T (exact in f32) ----------------
__global__ void wino_w_kernel(const float* __restrict__ w) {
    int idx = blockIdx.x * 256 + threadIdx.x;      // (k, c)
    if (idx >= K_ * C_) return;
    const float* gp = w + (size_t)idx * 9;
    float gg[3][3];
    #pragma unroll
    for (int r = 0; r < 3; ++r)
        #pragma unroll
        for (int s = 0; s < 3; ++s)
            gg[r][s] = quant16f(gp[r * 3 + s]);
    float tr[4][3];
    #pragma unroll
    for (int s = 0; s < 3; ++s) {
        tr[0][s] = gg[0][s];
        tr[1][s] = 0.5f * (gg[0][s] + gg[1][s] + gg[2][s]);
        tr[2][s] = 0.5f * (gg[0][s] - gg[1][s] + gg[2][s]);
        tr[3][s] = gg[2][s];
    }
    #pragma unroll
    for (int a = 0; a < 4; ++a) {
        float u0 = tr[a][0];
        float u1 = 0.5f * (tr[a][0] + tr[a][1] + tr[a][2]);
        float u2 = 0.5f * (tr[a][0] - tr[a][1] + tr[a][2]);
        float u3 = tr[a][2];
        g_U[(a * 4 + 0) * (K_ * C_) + idx] = __float2half_rn(u0);
        g_U[(a * 4 + 1) * (K_ * C_) + idx] = __float2half_rn(u1);
        g_U[(a * 4 + 2) * (K_ * C_) + idx] = __float2half_rn(u2);
        g_U[(a * 4 + 3) * (K_ * C_) + idx] = __float2half_rn(u3);
    }
}

// ---------------- input transform: V = B^T d B (fp32 internal) ----------------
__global__ __launch_bounds__(256) void wino_in_kernel() {
    const int tid = threadIdx.x;
    const int c2  = tid & 63;
    const int p   = blockIdx.x * 4 + (tid >> 6);
    const int n   = p / TPI;
    const int t   = p % TPI;
    const int ty  = t / 28, tx = t % 28;

    const __half2* src = reinterpret_cast<const __half2*>(g_xp)
        + ((size_t)(n * HP_ + 2 * ty) * WP_ + 2 * tx) * (C_ / 2) + c2;
    const int rstr = WP_ * (C_ / 2);
    const int cstr = C_ / 2;

    float2 d[4][4];
    #pragma unroll
    for (int i = 0; i < 4; ++i)
        #pragma unroll
        for (int j = 0; j < 4; ++j)
            d[i][j] = __half22float2(src[i * rstr + j * cstr]);

    float2 tt[4][4];
    #pragma unroll
    for (int j = 0; j < 4; ++j) {
        tt[0][j] = make_float2(d[0][j].x - d[2][j].x, d[0][j].y - d[2][j].y);
        tt[1][j] = make_float2(d[1][j].x + d[2][j].x, d[1][j].y + d[2][j].y);
        tt[2][j] = make_float2(d[2][j].x - d[1][j].x, d[2][j].y - d[1][j].y);
        tt[3][j] = make_float2(d[1][j].x - d[3][j].x, d[1][j].y - d[3][j].y);
    }
    __half2* dst = reinterpret_cast<__half2*>(g_V) + c2 + (size_t)p * (C_ / 2);
    const size_t plane = (size_t)P_TOT * (C_ / 2);
    #pragma unroll
    for (int a = 0; a < 4; ++a) {
        float2 v0 = make_float2(tt[a][0].x - tt[a][2].x, tt[a][0].y - tt[a][2].y);
        float2 v1 = make_float2(tt[a][1].x + tt[a][2].x, tt[a][1].y + tt[a][2].y);
        float2 v2 = make_float2(tt[a][2].x - tt[a][1].x, tt[a][2].y - tt[a][1].y);
        float2 v3 = make_float2(tt[a][1].x - tt[a][3].x, tt[a][1].y - tt[a][3].y);
        dst[(a * 4 + 0) * plane] = __floats2half2_rn(v0.x, v0.y);
        dst[(a * 4 + 1) * plane] = __floats2half2_rn(v1.x, v1.y);
        dst[(a * 4 + 2) * plane] = __floats2half2_rn(v2.x, v2.y);
        dst[(a * 4 + 3) * plane] = __floats2half2_rn(v3.x, v3.y);
    }
}

// ---------------- compile-time fold: Y += (AT[iy] x AT[jx]) * M ----------------
template <int G00, int G01, int G10, int G11>
__device__ __forceinline__ void fold_xi(float (&acc)[2][4][4], float (&Y)[2][4][4][4]) {
    #pragma unroll
    for (int i = 0; i < 2; ++i)
        #pragma unroll
        for (int j = 0; j < 4; ++j)
            #pragma unroll
            for (int e = 0; e < 4; ++e) {
                const float m = acc[i][j][e];
                if (G00 == 1) Y[i][j][e][0] += m; else if (G00 == -1) Y[i][j][e][0] -= m;
                if (G01 == 1) Y[i][j][e][1] += m; else if (G01 == -1) Y[i][j][e][1] -= m;
                if (G10 == 1) Y[i][j][e][2] += m; else if (G10 == -1) Y[i][j][e][2] -= m;
                if (G11 == 1) Y[i][j][e][3] += m; else if (G11 == -1) Y[i][j][e][3] -= m;
                acc[i][j][e] = 0.0f;
            }
}

// ---------------- fused GEMM + output transform ----------------
// grid (392, 2), 256 threads, 8 warps (4M x 2N), warp tile 32x32.
// CTA: 128 k-out x 64 wino tiles; 16 stages (one xi each, BK=128),
// compile-time fold into Y accumulators, NCHW epilogue.
__global__ __launch_bounds__(256, 1) void wino_fused_kernel(float* __restrict__ out) {
    extern __shared__ __align__(128) __half smem[];
    const uint32_t sbase = smem_u32(smem);

    const int tid  = threadIdx.x;
    const int lane = tid & 31;
    const int wid  = tid >> 5;
    const int warpM = wid & 3;          // 4 warps along M (32 rows)
    const int warpN = wid >> 2;         // 2 warps along N (32 tiles)
    const int g  = lane >> 2;
    const int tg = lane & 3;

    const int p0 = blockIdx.x * GBN;
    const int k0 = blockIdx.y * GBM;

    // loader mapping (full xi per stage: 128 halves = 16 chunks per row)
    const int aRow = tid >> 1;                    // 128 rows, 2 thr/row
    const int ac0  = (tid & 1) * 8;               // 8 contiguous chunks
    const int bRow = tid >> 2;                    // 64 rows, 4 thr/row
    const int bc0  = (tid & 3) * 4;               // 4 contiguous chunks
    const __half* aGbase = g_U + (size_t)(k0 + aRow) * C_ + ac0 * 8;
    const __half* bGbase = g_V + (size_t)(p0 + bRow) * C_ + bc0 * 8;

    // fragment ldmatrix bases
    const uint32_t fragSel = ((lane & 15) * PITCH + ((lane >> 4) << 3)) * 2;
    const uint32_t aFragBase = sbase + (uint32_t)(warpM * 32 * PITCH * 2) + fragSel;
    const uint32_t bFragBase = sbase + (uint32_t)SA_BYTES
                             + (uint32_t)(warpN * 32 * PITCH * 2) + fragSel;

    float acc[2][4][4];
    float Y[2][4][4][4];
    #pragma unroll
    for (int i = 0; i < 2; ++i)
        #pragma unroll
        for (int j = 0; j < 4; ++j)
            #pragma unroll
            for (int e = 0; e < 4; ++e) {
                acc[i][j][e] = 0.0f;
                #pragma unroll
                for (int q = 0; q < 4; ++q) Y[i][j][e][q] = 0.0f;
            }

    auto load_stage = [&](int xi) {
        const uint32_t sA = sbase + (uint32_t)((xi % 3) * STAGE_BYTES);
        const uint32_t sB = sA + SA_BYTES;
        const __half* asrc = aGbase + (size_t)xi * (K_ * C_);
        const __half* bsrc = bGbase + (size_t)xi * ((size_t)P_TOT * C_);
        #pragma unroll
        for (int j = 0; j < 8; ++j)
            CP16(sA + (aRow * PITCH + (ac0 + j) * 8) * 2, asrc + j * 8);
        #pragma unroll
        for (int j = 0; j < 4; ++j)
            CP16(sB + (bRow * PITCH + (bc0 + j) * 8) * 2, bsrc + j * 8);
    };

    auto compute = [&](int buf) {
        const uint32_t off = (uint32_t)(buf * STAGE_BYTES);
        #pragma unroll
        for (int kk = 0; kk < 8; ++kk) {
            const uint32_t kcb = (uint32_t)(kk * 32);
            uint32_t a[2][4], b[4][2];
            #pragma unroll
            for (int i = 0; i < 2; ++i)
                LDSM_X4(a[i][0], a[i][1], a[i][2], a[i][3],
                        aFragBase + off + kcb + i * (16 * PITCH * 2));
            #pragma unroll
            for (int jj = 0; jj < 2; ++jj)
                LDSM_X4(b[2 * jj][0], b[2 * jj + 1][0], b[2 * jj][1], b[2 * jj + 1][1],
                        bFragBase + off + kcb + jj * (16 * PITCH * 2));
            #pragma unroll
            for (int i = 0; i < 2; ++i)
                #pragma unroll
                for (int j = 0; j < 4; ++j)
                    asm volatile(
                        "mma.sync.aligned.m16n8k16.row.col.f32.f16.f16.f32 "
                        "{%0,%1,%2,%3}, {%4,%5,%6,%7}, {%8,%9}, {%0,%1,%2,%3};\n"
                        : "+f"(acc[i][j][0]), "+f"(acc[i][j][1]),
                          "+f"(acc[i][j][2]), "+f"(acc[i][j][3])
                        : "r"(a[i][0]), "r"(a[i][1]), "r"(a[i][2]), "r"(a[i][3]),
                          "r"(b[j][0]), "r"(b[j][1]));
        }
    };

    // ---- pipeline over 16 xi stages ----
    load_stage(0); CP_COMMIT();
    load_stage(1); CP_COMMIT();

    #pragma unroll 1
    for (int s = 0; s < NST; ++s) {
        if (s < NST - 1) { CP_WAIT1(); } else { CP_WAIT0(); }
        __syncthreads();
        if (s + 2 < NST) { load_stage(s + 2); CP_COMMIT(); }
        compute(s % 3);

        switch (s) {   // compile-time AT[iy] x AT[jx] coefficients
            case 0:  fold_xi< 1, 0, 0, 0>(acc, Y); break;
            case 1:  fold_xi< 1, 1, 0, 0>(acc, Y); break;
            case 2:  fold_xi< 1,-1, 0, 0>(acc, Y); break;
            case 3:  fold_xi< 0,-1, 0, 0>(acc, Y); break;
            case 4:  fold_xi< 1, 0, 1, 0>(acc, Y); break;
            case 5:  fold_xi< 1, 1, 1, 1>(acc, Y); break;
            case 6:  fold_xi< 1,-1, 1,-1>(acc, Y); break;
            case 7:  fold_xi< 0,-1, 0,-1>(acc, Y); break;
            case 8:  fold_xi< 1, 0,-1, 0>(acc, Y); break;
            case 9:  fold_xi< 1, 1,-1,-1>(acc, Y); break;
            case 10: fold_xi< 1,-1,-1, 1>(acc, Y); break;
            case 11: fold_xi< 0,-1, 0, 1>(acc, Y); break;
            case 12: fold_xi< 0, 0,-1, 0>(acc, Y); break;
            case 13: fold_xi< 0, 0,-1,-1>(acc, Y); break;
            case 14: fold_xi< 0, 0,-1, 1>(acc, Y); break;
            case 15: fold_xi< 0, 0, 0, 1>(acc, Y); break;   // g11 = (-1)*(-1) = +1 (R12 bug: was -1)
        }
    }

    // ---- epilogue: Y -> NCHW output (2x2 patch per cell) ----
    #pragma unroll
    for (int i = 0; i < 2; ++i) {
        #pragma unroll
        for (int j = 0; j < 4; ++j) {
            #pragma unroll
            for (int e = 0; e < 4; ++e) {
                const int k = k0 + warpM * 32 + i * 16 + g + ((e >> 1) << 3);
                const int p = p0 + warpN * 32 + j * 8 + tg * 2 + (e & 1);
                const int n  = p / TPI;
                const int t  = p % TPI;
                const int ty = t / 28, tx = t % 28;
                float* o = out + (((size_t)(n * K_ + k) * H_) + 2 * ty) * W_ + 2 * tx;
                *reinterpret_cast<float2*>(o)      = make_float2(Y[i][j][e][0], Y[i][j][e][1]);
                *reinterpret_cast<float2*>(o + W_) = make_float2(Y[i][j][e][2], Y[i][j][e][3]);
            }
        }
    }
}

extern "C" void kernel_launch(void* const* d_in, const int* in_sizes, int n_in,
                              void* d_out, int out_size) {
    const float* x   = (const float*)d_in[0];   // (32,128,56,56) f32
    const float* wgt = (const float*)d_in[1];   // (256,128,3,3)  f32

    zero_border_kernel<<<N_ * HP_, 128>>>();
    xform_x_kernel<<<dim3(N_, H_), 256>>>(x);
    wino_w_kernel<<<(K_ * C_ + 255) / 256, 256>>>(wgt);
    wino_in_kernel<<<P_TOT / 4, 256>>>();

    static bool attr_set = false;
    if (!attr_set) {
        cudaFuncSetAttribute(wino_fused_kernel,
                             cudaFuncAttributeMaxDynamicSharedMemorySize, SMEM_TOTAL);
        attr_set = true;
    }
    wino_fused_kernel<<<dim3(P_TOT / GBN, K_ / GBM), 256, SMEM_TOTAL>>>((float*)d_out);
}

// round 14
// speedup vs baseline: 1.2806x; 1.2806x over previous
#include <cuda_runtime.h>
#include <cuda_fp16.h>
#include <cstdint>

// ---------------- problem constants ----------------
#define N_    32
#define C_    128
#define H_    56
#define W_    56
#define K_    256
#define HW_   3136
#define HP_   58
#define WP_   58
#define TPI   784            // winograd tiles per image (28*28)
#define P_TOT 25088          // 32 * 784

// ---------------- fused GEMM tiling ----------------
#define GBM   128            // k-out per CTA
#define GBN   64             // winograd tiles per CTA
#define NST   32             // 16 xi * 2 stages (BK=64)
#define PITCH 72             // halves per smem row -> conflict-free LDSM
#define SA_BYTES (GBM * PITCH * 2)              // 18432
#define SB_BYTES (GBN * PITCH * 2)              // 9216
#define STAGE_BYTES (SA_BYTES + SB_BYTES)       // 27648
#define SMEM_TOTAL (3 * STAGE_BYTES)            // 82944

// ---------------- scratch ----------------
__device__ alignas(1024) __half g_xp[(size_t)N_ * HP_ * WP_ * C_];       // padded NHWC fp16
__device__ alignas(1024) __half g_U[16 * K_ * C_];                       // wino weights [xi][k][c]
__device__ alignas(1024) __half g_V[(size_t)16 * P_TOT * C_];            // wino inputs  [xi][p][c]

// ---------------- helpers ----------------
__device__ __forceinline__ uint32_t smem_u32(const void* p) {
    uint32_t a;
    asm("{ .reg .u64 t; cvta.to.shared.u64 t, %1; cvt.u32.u64 %0, t; }" : "=r"(a) : "l"(p));
    return a;
}
#define CP16(dst, src) \
    asm volatile("cp.async.cg.shared.global [%0], [%1], 16;" :: "r"(dst), "l"(src) : "memory")
#define CP_COMMIT() asm volatile("cp.async.commit_group;" ::: "memory")
#define CP_WAIT1()  asm volatile("cp.async.wait_group 1;" ::: "memory")
#define CP_WAIT0()  asm volatile("cp.async.wait_group 0;" ::: "memory")
#define LDSM_X4(r0, r1, r2, r3, addr) \
    asm volatile("ldmatrix.sync.aligned.m8n8.x4.shared.b16 {%0,%1,%2,%3}, [%4];" \
        : "=r"(r0), "=r"(r1), "=r"(r2), "=r"(r3) : "r"(addr))

__device__ __forceinline__ float quant16f(float x) {
    float r = rintf(x * 4096.0f);
    r = fminf(fmaxf(r, -32768.0f), 32767.0f);
    return r * (1.0f / 4096.0f);
}

// ---------------- prepass: quantize + pad input ----------------
__global__ void zero_border_kernel() {
    int b = blockIdx.x;              // 32*58
    int n = b / HP_, hp = b % HP_;
    __half* rowp = g_xp + ((size_t)(n * HP_ + hp)) * WP_ * C_;
    uint4 z = make_uint4(0, 0, 0, 0);
    if (hp == 0 || hp == HP_ - 1) {
        for (int i = threadIdx.x; i < WP_ * C_ / 8; i += blockDim.x)
            reinterpret_cast<uint4*>(rowp)[i] = z;
    } else {
        if (threadIdx.x < 32) {
            int side = threadIdx.x >> 4;
            int q    = threadIdx.x & 15;
            __half* colp = rowp + (side ? (size_t)(WP_ - 1) * C_ : 0);
            reinterpret_cast<uint4*>(colp)[q] = z;
        }
    }
}

__global__ void xform_x_kernel(const float* __restrict__ x) {
    __shared__ __half st[W_ * C_];
    const int n = blockIdx.x, h = blockIdx.y;
    const int tid = threadIdx.x;
    const int c  = tid >> 1;
    const int wh = (tid & 1) * 28;
    const float* src = x + ((size_t)(n * C_ + c) * H_ + h) * W_ + wh;
    #pragma unroll
    for (int j = 0; j < 7; ++j) {
        float4 v = *reinterpret_cast<const float4*>(src + 4 * j);
        int wb = wh + 4 * j;
        st[(wb + 0) * C_ + c] = __float2half_rn(quant16f(v.x));
        st[(wb + 1) * C_ + c] = __float2half_rn(quant16f(v.y));
        st[(wb + 2) * C_ + c] = __float2half_rn(quant16f(v.z));
        st[(wb + 3) * C_ + c] = __float2half_rn(quant16f(v.w));
    }
    __syncthreads();
    __half* dst = g_xp + ((size_t)((n * HP_ + h + 1) * WP_ + 1)) * C_;
    for (int idx = tid; idx < W_ * C_ / 8; idx += 256) {
        int w = idx >> 4, q = idx & 15;
        reinterpret_cast<uint4*>(dst + (size_t)w * C_)[q] =
            reinterpret_cast<const uint4*>(st + w * C_)[q];
    }
}

// ---------------- weight transform: U = G g G^T (exact in f32) ----------------
__global__ void wino_w_kernel(const float* __restrict__ w) {
    int idx = blockIdx.x * 256 + threadIdx.x;      // (k, c)
    if (idx >= K_ * C_) return;
    const float* gp = w + (size_t)idx * 9;
    float gg[3][3];
    #pragma unroll
    for (int r = 0; r < 3; ++r)
        #pragma unroll
        for (int s = 0; s < 3; ++s)
            gg[r][s] = quant16f(gp[r * 3 + s]);
    float tr[4][3];
    #pragma unroll
    for (int s = 0; s < 3; ++s) {
        tr[0][s] = gg[0][s];
        tr[1][s] = 0.5f * (gg[0][s] + gg[1][s] + gg[2][s]);
        tr[2][s] = 0.5f * (gg[0][s] - gg[1][s] + gg[2][s]);
        tr[3][s] = gg[2][s];
    }
    #pragma unroll
    for (int a = 0; a < 4; ++a) {
        float u0 = tr[a][0];
        float u1 = 0.5f * (tr[a][0] + tr[a][1] + tr[a][2]);
        float u2 = 0.5f * (tr[a][0] - tr[a][1] + tr[a][2]);
        float u3 = tr[a][2];
        g_U[(a * 4 + 0) * (K_ * C_) + idx] = __float2half_rn(u0);
        g_U[(a * 4 + 1) * (K_ * C_) + idx] = __float2half_rn(u1);
        g_U[(a * 4 + 2) * (K_ * C_) + idx] = __float2half_rn(u2);
        g_U[(a * 4 + 3) * (K_ * C_) + idx] = __float2half_rn(u3);
    }
}

// ---------------- input transform: V = B^T d B (fp32 internal) ----------------
__global__ __launch_bounds__(256) void wino_in_kernel() {
    const int tid = threadIdx.x;
    const int c2  = tid & 63;
    const int p   = blockIdx.x * 4 + (tid >> 6);
    const int n   = p / TPI;
    const int t   = p % TPI;
    const int ty  = t / 28, tx = t % 28;

    const __half2* src = reinterpret_cast<const __half2*>(g_xp)
        + ((size_t)(n * HP_ + 2 * ty) * WP_ + 2 * tx) * (C_ / 2) + c2;
    const int rstr = WP_ * (C_ / 2);
    const int cstr = C_ / 2;

    float2 d[4][4];
    #pragma unroll
    for (int i = 0; i < 4; ++i)
        #pragma unroll
        for (int j = 0; j < 4; ++j)
            d[i][j] = __half22float2(src[i * rstr + j * cstr]);

    float2 tt[4][4];
    #pragma unroll
    for (int j = 0; j < 4; ++j) {
        tt[0][j] = make_float2(d[0][j].x - d[2][j].x, d[0][j].y - d[2][j].y);
        tt[1][j] = make_float2(d[1][j].x + d[2][j].x, d[1][j].y + d[2][j].y);
        tt[2][j] = make_float2(d[2][j].x - d[1][j].x, d[2][j].y - d[1][j].y);
        tt[3][j] = make_float2(d[1][j].x - d[3][j].x, d[1][j].y - d[3][j].y);
    }
    __half2* dst = reinterpret_cast<__half2*>(g_V) + c2 + (size_t)p * (C_ / 2);
    const size_t plane = (size_t)P_TOT * (C_ / 2);
    #pragma unroll
    for (int a = 0; a < 4; ++a) {
        float2 v0 = make_float2(tt[a][0].x - tt[a][2].x, tt[a][0].y - tt[a][2].y);
        float2 v1 = make_float2(tt[a][1].x + tt[a][2].x, tt[a][1].y + tt[a][2].y);
        float2 v2 = make_float2(tt[a][2].x - tt[a][1].x, tt[a][2].y - tt[a][1].y);
        float2 v3 = make_float2(tt[a][1].x - tt[a][3].x, tt[a][1].y - tt[a][3].y);
        dst[(a * 4 + 0) * plane] = __floats2half2_rn(v0.x, v0.y);
        dst[(a * 4 + 1) * plane] = __floats2half2_rn(v1.x, v1.y);
        dst[(a * 4 + 2) * plane] = __floats2half2_rn(v2.x, v2.y);
        dst[(a * 4 + 3) * plane] = __floats2half2_rn(v3.x, v3.y);
    }
}

// ---------------- compile-time fold: Y += (AT[iy] x AT[jx]) * M ----------------
template <int G00, int G01, int G10, int G11>
__device__ __forceinline__ void fold_xi(float (&acc)[2][2][4], float (&Y)[2][2][4][4]) {
    #pragma unroll
    for (int i = 0; i < 2; ++i)
        #pragma unroll
        for (int j = 0; j < 2; ++j)
            #pragma unroll
            for (int e = 0; e < 4; ++e) {
                const float m = acc[i][j][e];
                if (G00 == 1) Y[i][j][e][0] += m; else if (G00 == -1) Y[i][j][e][0] -= m;
                if (G01 == 1) Y[i][j][e][1] += m; else if (G01 == -1) Y[i][j][e][1] -= m;
                if (G10 == 1) Y[i][j][e][2] += m; else if (G10 == -1) Y[i][j][e][2] -= m;
                if (G11 == 1) Y[i][j][e][3] += m; else if (G11 == -1) Y[i][j][e][3] -= m;
                acc[i][j][e] = 0.0f;
            }
}

// ---------------- fused GEMM + output transform ----------------
// grid (392, 2), 512 threads, 16 warps (4M x 4N), warp tile 32x16.
// CTA: 128 k-out x 64 wino tiles; 32 stages (BK=64, 2 per xi),
// compile-time fold into Y accumulators, NCHW epilogue.
__global__ __launch_bounds__(512, 1) void wino_fused_kernel(float* __restrict__ out) {
    extern __shared__ __align__(128) __half smem[];
    const uint32_t sbase = smem_u32(smem);

    const int tid  = threadIdx.x;
    const int lane = tid & 31;
    const int wid  = tid >> 5;          // 0..15
    const int warpM = wid & 3;          // 4 warps along M (32 rows)
    const int warpN = wid >> 2;         // 4 warps along N (16 tiles)
    const int g  = lane >> 2;
    const int tg = lane & 3;

    const int p0 = blockIdx.x * GBN;
    const int k0 = blockIdx.y * GBM;

    // loader mapping (BK=64 per stage; 512 threads)
    const int aRow = tid >> 2;                    // 128 rows, 4 thr/row
    const int ac0  = (tid & 3) * 2;               // 2 contiguous chunks
    const int bRow = tid >> 3;                    // 64 rows, 8 thr/row
    const int bc   = tid & 7;                     // 1 chunk
    const __half* aGbase = g_U + (size_t)(k0 + aRow) * C_ + ac0 * 8;
    const __half* bGbase = g_V + (size_t)(p0 + bRow) * C_ + bc * 8;

    // fragment ldmatrix bases
    const uint32_t fragSel = ((lane & 15) * PITCH + ((lane >> 4) << 3)) * 2;
    const uint32_t aFragBase = sbase + (uint32_t)(warpM * 32 * PITCH * 2) + fragSel;
    const uint32_t bFragBase = sbase + (uint32_t)SA_BYTES
                             + (uint32_t)(warpN * 16 * PITCH * 2) + fragSel;

    float acc[2][2][4];
    float Y[2][2][4][4];
    #pragma unroll
    for (int i = 0; i < 2; ++i)
        #pragma unroll
        for (int j = 0; j < 2; ++j)
            #pragma unroll
            for (int e = 0; e < 4; ++e) {
                acc[i][j][e] = 0.0f;
                #pragma unroll
                for (int q = 0; q < 4; ++q) Y[i][j][e][q] = 0.0f;
            }

    auto load_stage = [&](int s) {
        const uint32_t sA = sbase + (uint32_t)((s % 3) * STAGE_BYTES);
        const uint32_t sB = sA + SA_BYTES;
        const int xi = s >> 1;
        const int hf = (s & 1) << 6;              // 0 or 64 halves in C
        const __half* asrc = aGbase + (size_t)xi * (K_ * C_) + hf;
        const __half* bsrc = bGbase + (size_t)xi * ((size_t)P_TOT * C_) + hf;
        #pragma unroll
        for (int j = 0; j < 2; ++j)
            CP16(sA + (aRow * PITCH + (ac0 + j) * 8) * 2, asrc + j * 8);
        CP16(sB + (bRow * PITCH + bc * 8) * 2, bsrc);
    };

    auto compute = [&](int buf) {
        const uint32_t off = (uint32_t)(buf * STAGE_BYTES);
        #pragma unroll
        for (int kk = 0; kk < 4; ++kk) {
            const uint32_t kcb = (uint32_t)(kk * 32);
            uint32_t a[2][4], b[2][2];
            #pragma unroll
            for (int i = 0; i < 2; ++i)
                LDSM_X4(a[i][0], a[i][1], a[i][2], a[i][3],
                        aFragBase + off + kcb + i * (16 * PITCH * 2));
            LDSM_X4(b[0][0], b[1][0], b[0][1], b[1][1],
                    bFragBase + off + kcb);
            #pragma unroll
            for (int i = 0; i < 2; ++i)
                #pragma unroll
                for (int j = 0; j < 2; ++j)
                    asm volatile(
                        "mma.sync.aligned.m16n8k16.row.col.f32.f16.f16.f32 "
                        "{%0,%1,%2,%3}, {%4,%5,%6,%7}, {%8,%9}, {%0,%1,%2,%3};\n"
                        : "+f"(acc[i][j][0]), "+f"(acc[i][j][1]),
                          "+f"(acc[i][j][2]), "+f"(acc[i][j][3])
                        : "r"(a[i][0]), "r"(a[i][1]), "r"(a[i][2]), "r"(a[i][3]),
                          "r"(b[j][0]), "r"(b[j][1]));
        }
    };

    // ---- pipeline over 32 stages (2 per xi) ----
    load_stage(0); CP_COMMIT();
    load_stage(1); CP_COMMIT();

    #pragma unroll 1
    for (int s = 0; s < NST; ++s) {
        if (s < NST - 1) { CP_WAIT1(); } else { CP_WAIT0(); }
        __syncthreads();
        if (s + 2 < NST) { load_stage(s + 2); CP_COMMIT(); }
        compute(s % 3);

        if (s & 1) {
            switch (s >> 1) {   // compile-time AT[iy] x AT[jx] coefficients
                case 0:  fold_xi< 1, 0, 0, 0>(acc, Y); break;
                case 1:  fold_xi< 1, 1, 0, 0>(acc, Y); break;
                case 2:  fold_xi< 1,-1, 0, 0>(acc, Y); break;
                case 3:  fold_xi< 0,-1, 0, 0>(acc, Y); break;
                case 4:  fold_xi< 1, 0, 1, 0>(acc, Y); break;
                case 5:  fold_xi< 1, 1, 1, 1>(acc, Y); break;
                case 6:  fold_xi< 1,-1, 1,-1>(acc, Y); break;
                case 7:  fold_xi< 0,-1, 0,-1>(acc, Y); break;
                case 8:  fold_xi< 1, 0,-1, 0>(acc, Y); break;
                case 9:  fold_xi< 1, 1,-1,-1>(acc, Y); break;
                case 10: fold_xi< 1,-1,-1, 1>(acc, Y); break;
                case 11: fold_xi< 0,-1, 0, 1>(acc, Y); break;
                case 12: fold_xi< 0, 0,-1, 0>(acc, Y); break;
                case 13: fold_xi< 0, 0,-1,-1>(acc, Y); break;
                case 14: fold_xi< 0, 0,-1, 1>(acc, Y); break;
                case 15: fold_xi< 0, 0, 0, 1>(acc, Y); break;  // g11 = (-1)(-1) = +1
            }
        }
    }

    // ---- epilogue: Y -> NCHW output (2x2 patch per cell) ----
    #pragma unroll
    for (int i = 0; i < 2; ++i) {
        #pragma unroll
        for (int j = 0; j < 2; ++j) {
            #pragma unroll
            for (int e = 0; e < 4; ++e) {
                const int k = k0 + warpM * 32 + i * 16 + g + ((e >> 1) << 3);
                const int p = p0 + warpN * 16 + j * 8 + tg * 2 + (e & 1);
                const int n  = p / TPI;
                const int t  = p % TPI;
                const int ty = t / 28, tx = t % 28;
                float* o = out + (((size_t)(n * K_ + k) * H_) + 2 * ty) * W_ + 2 * tx;
                *reinterpret_cast<float2*>(o)      = make_float2(Y[i][j][e][0], Y[i][j][e][1]);
                *reinterpret_cast<float2*>(o + W_) = make_float2(Y[i][j][e][2], Y[i][j][e][3]);
            }
        }
    }
}

extern "C" void kernel_launch(void* const* d_in, const int* in_sizes, int n_in,
                              void* d_out, int out_size) {
    const float* x   = (const float*)d_in[0];   // (32,128,56,56) f32
    const float* wgt = (const float*)d_in[1];   // (256,128,3,3)  f32

    zero_border_kernel<<<N_ * HP_, 128>>>();
    xform_x_kernel<<<dim3(N_, H_), 256>>>(x);
    wino_w_kernel<<<(K_ * C_ + 255) / 256, 256>>>(wgt);
    wino_in_kernel<<<P_TOT / 4, 256>>>();

    static bool attr_set = false;
    if (!attr_set) {
        cudaFuncSetAttribute(wino_fused_kernel,
                             cudaFuncAttributeMaxDynamicSharedMemorySize, SMEM_TOTAL);
        attr_set = true;
    }
    wino_fused_kernel<<<dim3(P_TOT / GBN, K_ / GBM), 512, SMEM_TOTAL>>>((float*)d_out);
}